// round 5
// baseline (speedup 1.0000x reference)
#include <cuda_runtime.h>
#include <math_constants.h>

#define GRID_MAX 4096
__device__ float    g_partial[GRID_MAX];  // per-block max (every used slot overwritten)
__device__ unsigned g_count;              // zero-init at load; last block resets each call

__device__ __forceinline__ void top2_update(float& t1, float& t2, float v) {
    t2 = fmaxf(t2, fminf(t1, v));
    t1 = fmaxf(t1, v);
}

// One WARP per row, all 7 heads. No shared memory / barriers in the row path.
template<int NV4>   // NV4 = C/4
__global__ __launch_bounds__(256) void ms_warp_row(
    const float* __restrict__ o1, const float* __restrict__ o2,
    const float* __restrict__ o3, const float* __restrict__ o4,
    const float* __restrict__ o5, const float* __restrict__ o6,
    const float* __restrict__ mimic,
    const int* __restrict__ targets,
    float* __restrict__ out_thresh,   // [N,7]
    float* __restrict__ out_max,      // out[0]
    int C, int N)
{
    const int wid  = threadIdx.x >> 5;
    const int lane = threadIdx.x & 31;
    const int nwarps = gridDim.x << 3;

    const float* heads[7] = {o1, o2, o3, o4, o5, o6, mimic};

    float warpmax = -CUDART_INF_F;

    for (int row = (blockIdx.x << 3) + wid; row < N; row += nwarps) {
        float t1[7], t2[7];

        #pragma unroll
        for (int h = 0; h < 7; ++h) {
            const float4* p4 = (const float4*)(heads[h] + (size_t)row * (size_t)C);
            constexpr int K = (NV4 + 31) / 32;   // 8 for NV4=250
            float4 v[K];
            #pragma unroll
            for (int k = 0; k < K; ++k) {
                int idx = lane + 32 * k;
                if (32 * k + 31 < NV4 || idx < NV4)
                    v[k] = p4[idx];
                else
                    v[k] = make_float4(-CUDART_INF_F, -CUDART_INF_F,
                                       -CUDART_INF_F, -CUDART_INF_F);
            }
            float a = -CUDART_INF_F, b = -CUDART_INF_F;
            #pragma unroll
            for (int k = 0; k < K; ++k) {
                top2_update(a, b, v[k].x);
                top2_update(a, b, v[k].y);
                top2_update(a, b, v[k].z);
                top2_update(a, b, v[k].w);
            }
            t1[h] = a; t2[h] = b;
        }

        // butterfly top-2 reduction: all lanes converge to the row result
        #pragma unroll
        for (int h = 0; h < 7; ++h) {
            #pragma unroll
            for (int off = 16; off; off >>= 1) {
                float u1 = __shfl_xor_sync(0xFFFFFFFFu, t1[h], off);
                float u2 = __shfl_xor_sync(0xFFFFFFFFu, t2[h], off);
                t2[h] = fmaxf(fmaxf(t2[h], u2), fminf(t1[h], u1));
                t1[h] = fmaxf(t1[h], u1);
            }
        }

        // running max over heads 0..5 (identical on all lanes)
        float bm = t1[0];
        #pragma unroll
        for (int h = 1; h < 6; ++h) bm = fmaxf(bm, t1[h]);
        warpmax = fmaxf(warpmax, bm);

        // lanes 0..6: margin of head==lane
        const int tgt = targets[row];
        float my_m = 0.0f;
        if (lane < 7) {
            const float* ph = o1;
            if (lane == 1) ph = o2;
            else if (lane == 2) ph = o3;
            else if (lane == 3) ph = o4;
            else if (lane == 4) ph = o5;
            else if (lane == 5) ph = o6;
            else if (lane == 6) ph = mimic;
            float tval = __ldg(ph + (size_t)row * (size_t)C + tgt);
            my_m = (tval == t1[lane]) ? (t1[lane] - t2[lane]) * 0.5f : 0.0f;
        }

        // gather all 7 margins, softmax; lanes 0..6 store their element
        float m[7], mx = -CUDART_INF_F;
        #pragma unroll
        for (int h = 0; h < 7; ++h) {
            m[h] = __shfl_sync(0xFFFFFFFFu, my_m, h);
            mx = fmaxf(mx, m[h]);
        }
        float sum = 0.0f;
        #pragma unroll
        for (int h = 0; h < 7; ++h) sum += __expf(m[h] - mx);
        if (lane < 7)
            out_thresh[(size_t)row * 7 + lane] = __expf(my_m - mx) / sum;
    }

    // ---- fused global-max tail ----
    __shared__ float s_w[8];
    __shared__ bool  s_last;
    if (lane == 0) s_w[wid] = warpmax;
    __syncthreads();
    if (threadIdx.x == 0) {
        float bm = s_w[0];
        #pragma unroll
        for (int w = 1; w < 8; ++w) bm = fmaxf(bm, s_w[w]);
        g_partial[blockIdx.x] = bm;
        __threadfence();
        unsigned old = atomicAdd(&g_count, 1u);
        s_last = (old == gridDim.x - 1);
    }
    __syncthreads();

    if (s_last) {
        float mv = -CUDART_INF_F;
        for (unsigned i = threadIdx.x; i < gridDim.x; i += blockDim.x)
            mv = fmaxf(mv, g_partial[i]);
        #pragma unroll
        for (int off = 16; off; off >>= 1)
            mv = fmaxf(mv, __shfl_xor_sync(0xFFFFFFFFu, mv, off));
        if (lane == 0) s_w[wid] = mv;
        __syncthreads();
        if (threadIdx.x == 0) {
            float r = s_w[0];
            #pragma unroll
            for (int w = 1; w < 8; ++w) r = fmaxf(r, s_w[w]);
            out_max[0] = r;
            g_count = 0;   // deterministic reset for next graph replay
        }
    }
}

// Generic fallback: runtime C, same warp-per-row structure.
__global__ __launch_bounds__(256) void ms_warp_row_gen(
    const float* __restrict__ o1, const float* __restrict__ o2,
    const float* __restrict__ o3, const float* __restrict__ o4,
    const float* __restrict__ o5, const float* __restrict__ o6,
    const float* __restrict__ mimic,
    const int* __restrict__ targets,
    float* __restrict__ out_thresh, float* __restrict__ out_max,
    int C, int N)
{
    const int wid  = threadIdx.x >> 5;
    const int lane = threadIdx.x & 31;
    const int nwarps = gridDim.x << 3;

    const float* heads[7] = {o1, o2, o3, o4, o5, o6, mimic};
    float warpmax = -CUDART_INF_F;

    for (int row = (blockIdx.x << 3) + wid; row < N; row += nwarps) {
        float t1[7], t2[7];
        #pragma unroll
        for (int h = 0; h < 7; ++h) {
            const float* p = heads[h] + (size_t)row * (size_t)C;
            float a = -CUDART_INF_F, b = -CUDART_INF_F;
            const int nv4 = C >> 2;
            const float4* p4 = (const float4*)p;
            for (int i = lane; i < nv4; i += 32) {
                float4 v = p4[i];
                top2_update(a, b, v.x); top2_update(a, b, v.y);
                top2_update(a, b, v.z); top2_update(a, b, v.w);
            }
            for (int i = (nv4 << 2) + lane; i < C; i += 32)
                top2_update(a, b, p[i]);
            t1[h] = a; t2[h] = b;
        }
        #pragma unroll
        for (int h = 0; h < 7; ++h) {
            #pragma unroll
            for (int off = 16; off; off >>= 1) {
                float u1 = __shfl_xor_sync(0xFFFFFFFFu, t1[h], off);
                float u2 = __shfl_xor_sync(0xFFFFFFFFu, t2[h], off);
                t2[h] = fmaxf(fmaxf(t2[h], u2), fminf(t1[h], u1));
                t1[h] = fmaxf(t1[h], u1);
            }
        }
        float bm = t1[0];
        #pragma unroll
        for (int h = 1; h < 6; ++h) bm = fmaxf(bm, t1[h]);
        warpmax = fmaxf(warpmax, bm);

        const int tgt = targets[row];
        float my_m = 0.0f;
        if (lane < 7) {
            const float* ph = o1;
            if (lane == 1) ph = o2;
            else if (lane == 2) ph = o3;
            else if (lane == 3) ph = o4;
            else if (lane == 4) ph = o5;
            else if (lane == 5) ph = o6;
            else if (lane == 6) ph = mimic;
            float tval = __ldg(ph + (size_t)row * (size_t)C + tgt);
            my_m = (tval == t1[lane]) ? (t1[lane] - t2[lane]) * 0.5f : 0.0f;
        }
        float m[7], mx = -CUDART_INF_F;
        #pragma unroll
        for (int h = 0; h < 7; ++h) {
            m[h] = __shfl_sync(0xFFFFFFFFu, my_m, h);
            mx = fmaxf(mx, m[h]);
        }
        float sum = 0.0f;
        #pragma unroll
        for (int h = 0; h < 7; ++h) sum += __expf(m[h] - mx);
        if (lane < 7)
            out_thresh[(size_t)row * 7 + lane] = __expf(my_m - mx) / sum;
    }

    __shared__ float s_w[8];
    __shared__ bool  s_last;
    if (lane == 0) s_w[wid] = warpmax;
    __syncthreads();
    if (threadIdx.x == 0) {
        float bm = s_w[0];
        #pragma unroll
        for (int w = 1; w < 8; ++w) bm = fmaxf(bm, s_w[w]);
        g_partial[blockIdx.x] = bm;
        __threadfence();
        unsigned old = atomicAdd(&g_count, 1u);
        s_last = (old == gridDim.x - 1);
    }
    __syncthreads();
    if (s_last) {
        float mv = -CUDART_INF_F;
        for (unsigned i = threadIdx.x; i < gridDim.x; i += blockDim.x)
            mv = fmaxf(mv, g_partial[i]);
        #pragma unroll
        for (int off = 16; off; off >>= 1)
            mv = fmaxf(mv, __shfl_xor_sync(0xFFFFFFFFu, mv, off));
        if (lane == 0) s_w[wid] = mv;
        __syncthreads();
        if (threadIdx.x == 0) {
            float r = s_w[0];
            #pragma unroll
            for (int w = 1; w < 8; ++w) r = fmaxf(r, s_w[w]);
            out_max[0] = r;
            g_count = 0;
        }
    }
}

extern "C" void kernel_launch(void* const* d_in, const int* in_sizes, int n_in,
                              void* d_out, int out_size) {
    const float* o1    = (const float*)d_in[0];
    const float* o2    = (const float*)d_in[1];
    const float* o3    = (const float*)d_in[2];
    const float* o4    = (const float*)d_in[3];
    const float* o5    = (const float*)d_in[4];
    const float* o6    = (const float*)d_in[5];
    const float* mimic = (const float*)d_in[6];
    const int*   tgt   = (const int*)d_in[7];

    const int N = in_sizes[7];            // 16384 rows
    const int C = in_sizes[0] / N;        // 1000 classes

    float* out = (float*)d_out;           // [0]=max_preds, [1..]=thresholds [N,7]

    int grid = (N + 7) >> 3;              // one row per warp
    if (grid > GRID_MAX) grid = GRID_MAX;

    if (C == 1000) {
        ms_warp_row<250><<<grid, 256>>>(o1, o2, o3, o4, o5, o6, mimic, tgt,
                                        out + 1, out, C, N);
    } else {
        ms_warp_row_gen<<<grid, 256>>>(o1, o2, o3, o4, o5, o6, mimic, tgt,
                                       out + 1, out, C, N);
    }
}

// round 6
// speedup vs baseline: 1.1266x; 1.1266x over previous
#include <cuda_runtime.h>
#include <math_constants.h>

#define MAX_N      65536
#define MAX_BLOCKS 65536
__device__ float g_margin[MAX_N * 7];      // pre-scaled margins (m/2), overwritten each call
__device__ float g_partial[MAX_BLOCKS];    // per-block head-max (heads 0..5), overwritten

__device__ __forceinline__ void top2_update(float& t1, float& t2, float v) {
    t2 = fmaxf(t2, fminf(t1, v));
    t1 = fmaxf(t1, v);
}

__device__ __forceinline__ float4 ldcs4(const float4* p) {
    return __ldcs(p);
}

// ---------- Kernel A: one warp per (row, head). No barriers in hot path. ----------
template<int NV4>   // NV4 = C/4
__global__ __launch_bounds__(256) void scan_kernel(
    const float* __restrict__ o1, const float* __restrict__ o2,
    const float* __restrict__ o3, const float* __restrict__ o4,
    const float* __restrict__ o5, const float* __restrict__ o6,
    const float* __restrict__ mimic,
    const int* __restrict__ targets,
    int C, int N)
{
    const int wid  = threadIdx.x >> 5;
    const int lane = threadIdx.x & 31;
    const int gw   = (blockIdx.x << 3) + wid;       // global warp id
    const int total = N * 7;

    __shared__ float s_top1[8];
    s_top1[wid] = -CUDART_INF_F;

    if (gw < total) {
        const int row = gw / 7;
        const int h   = gw - row * 7;

        const float* heads[7] = {o1, o2, o3, o4, o5, o6, mimic};
        const float* p = heads[h] + (size_t)row * (size_t)C;
        const float4* p4 = (const float4*)p;

        // prefetch target value early so it overlaps the scan
        const int tgt = targets[row];
        float tval = (lane == 0) ? __ldg(p + tgt) : 0.0f;

        constexpr int K = (NV4 + 31) / 32;           // 8 for NV4=250
        float4 v[K];
        #pragma unroll
        for (int k = 0; k < K; ++k) {
            int idx = lane + 32 * k;
            if (32 * k + 31 < NV4 || idx < NV4)
                v[k] = ldcs4(p4 + idx);
            else
                v[k] = make_float4(-CUDART_INF_F, -CUDART_INF_F,
                                   -CUDART_INF_F, -CUDART_INF_F);
        }

        float t1 = -CUDART_INF_F, t2 = -CUDART_INF_F;
        #pragma unroll
        for (int k = 0; k < K; ++k) {
            top2_update(t1, t2, v[k].x);
            top2_update(t1, t2, v[k].y);
            top2_update(t1, t2, v[k].z);
            top2_update(t1, t2, v[k].w);
        }

        #pragma unroll
        for (int off = 16; off; off >>= 1) {
            float u1 = __shfl_down_sync(0xFFFFFFFFu, t1, off);
            float u2 = __shfl_down_sync(0xFFFFFFFFu, t2, off);
            t2 = fmaxf(fmaxf(t2, u2), fminf(t1, u1));
            t1 = fmaxf(t1, u1);
        }

        if (lane == 0) {
            g_margin[gw] = (tval == t1) ? (t1 - t2) * 0.5f : 0.0f;
            if (h < 6) s_top1[wid] = t1;
        }
    }
    __syncthreads();  // one-shot, end of block

    if (threadIdx.x == 0) {
        float bm = s_top1[0];
        #pragma unroll
        for (int w = 1; w < 8; ++w) bm = fmaxf(bm, s_top1[w]);
        g_partial[blockIdx.x] = bm;
    }
}

// Generic fallback: runtime C.
__global__ __launch_bounds__(256) void scan_kernel_gen(
    const float* __restrict__ o1, const float* __restrict__ o2,
    const float* __restrict__ o3, const float* __restrict__ o4,
    const float* __restrict__ o5, const float* __restrict__ o6,
    const float* __restrict__ mimic,
    const int* __restrict__ targets,
    int C, int N)
{
    const int wid  = threadIdx.x >> 5;
    const int lane = threadIdx.x & 31;
    const int gw   = (blockIdx.x << 3) + wid;
    const int total = N * 7;

    __shared__ float s_top1[8];
    s_top1[wid] = -CUDART_INF_F;

    if (gw < total) {
        const int row = gw / 7;
        const int h   = gw - row * 7;

        const float* heads[7] = {o1, o2, o3, o4, o5, o6, mimic};
        const float* p = heads[h] + (size_t)row * (size_t)C;

        const int tgt = targets[row];
        float tval = (lane == 0) ? __ldg(p + tgt) : 0.0f;

        float t1 = -CUDART_INF_F, t2 = -CUDART_INF_F;
        const int nv4 = C >> 2;
        const float4* p4 = (const float4*)p;
        for (int i = lane; i < nv4; i += 32) {
            float4 v = __ldcs(p4 + i);
            top2_update(t1, t2, v.x); top2_update(t1, t2, v.y);
            top2_update(t1, t2, v.z); top2_update(t1, t2, v.w);
        }
        for (int i = (nv4 << 2) + lane; i < C; i += 32)
            top2_update(t1, t2, p[i]);

        #pragma unroll
        for (int off = 16; off; off >>= 1) {
            float u1 = __shfl_down_sync(0xFFFFFFFFu, t1, off);
            float u2 = __shfl_down_sync(0xFFFFFFFFu, t2, off);
            t2 = fmaxf(fmaxf(t2, u2), fminf(t1, u1));
            t1 = fmaxf(t1, u1);
        }

        if (lane == 0) {
            g_margin[gw] = (tval == t1) ? (t1 - t2) * 0.5f : 0.0f;
            if (h < 6) s_top1[wid] = t1;
        }
    }
    __syncthreads();

    if (threadIdx.x == 0) {
        float bm = s_top1[0];
        #pragma unroll
        for (int w = 1; w < 8; ++w) bm = fmaxf(bm, s_top1[w]);
        g_partial[blockIdx.x] = bm;
    }
}

// ---------- Kernel B: softmax per row + global max (block 0). L2-hot. ----------
__global__ __launch_bounds__(256) void finalize_kernel(
    float* __restrict__ out,          // out[0]=max, out+1 = thresholds [N,7]
    int N, int nblocks)
{
    // block 0 additionally reduces g_partial -> out[0]
    if (blockIdx.x == 0) {
        __shared__ float s[8];
        float m = -CUDART_INF_F;
        for (int i = threadIdx.x; i < nblocks; i += 256)
            m = fmaxf(m, g_partial[i]);
        #pragma unroll
        for (int off = 16; off; off >>= 1)
            m = fmaxf(m, __shfl_xor_sync(0xFFFFFFFFu, m, off));
        if ((threadIdx.x & 31) == 0) s[threadIdx.x >> 5] = m;
        __syncthreads();
        if (threadIdx.x == 0) {
            float r = s[0];
            #pragma unroll
            for (int w = 1; w < 8; ++w) r = fmaxf(r, s[w]);
            out[0] = r;
        }
    }

    // all blocks: one thread per row, 7-way softmax of pre-scaled margins
    float* thr = out + 1;
    for (int row = blockIdx.x * 256 + threadIdx.x; row < N; row += gridDim.x * 256) {
        const float* mp = g_margin + row * 7;
        float m[7], mx = -CUDART_INF_F;
        #pragma unroll
        for (int h = 0; h < 7; ++h) { m[h] = mp[h]; mx = fmaxf(mx, m[h]); }
        float e[7], sum = 0.0f;
        #pragma unroll
        for (int h = 0; h < 7; ++h) { e[h] = __expf(m[h] - mx); sum += e[h]; }
        float inv = 1.0f / sum;
        float* o = thr + (size_t)row * 7;
        #pragma unroll
        for (int h = 0; h < 7; ++h) o[h] = e[h] * inv;
    }
}

extern "C" void kernel_launch(void* const* d_in, const int* in_sizes, int n_in,
                              void* d_out, int out_size) {
    const float* o1    = (const float*)d_in[0];
    const float* o2    = (const float*)d_in[1];
    const float* o3    = (const float*)d_in[2];
    const float* o4    = (const float*)d_in[3];
    const float* o5    = (const float*)d_in[4];
    const float* o6    = (const float*)d_in[5];
    const float* mimic = (const float*)d_in[6];
    const int*   tgt   = (const int*)d_in[7];

    const int N = in_sizes[7];            // 16384 rows
    const int C = in_sizes[0] / N;        // 1000 classes

    float* out = (float*)d_out;

    const int total_warps = N * 7;                  // 114688
    int grid = (total_warps + 7) >> 3;              // 14336 blocks of 8 warps
    if (grid > MAX_BLOCKS) grid = MAX_BLOCKS;

    if (C == 1000) {
        scan_kernel<250><<<grid, 256>>>(o1, o2, o3, o4, o5, o6, mimic, tgt, C, N);
    } else {
        scan_kernel_gen<<<grid, 256>>>(o1, o2, o3, o4, o5, o6, mimic, tgt, C, N);
    }
    finalize_kernel<<<256, 256>>>(out, N, grid);
}